// round 4
// baseline (speedup 1.0000x reference)
#include <cuda_runtime.h>
#include <cuda_bf16.h>
#include <math.h>
#include <stdint.h>

#define NN 4096
#define IN_DIM 512
#define OUT_DIM 512
#define HEADS 4
#define DK 128
#define KT 64                    // j-tile
#define SW_PAD 68                // weight-tile row stride (words)
#define SW_W (128 * SW_PAD)      // weight plane words (8704)
#define FR_PAD 36                // frag lane stride (words): LDS.128 conflict-free
#define FR_W (8 * 32 * FR_PAD)   // frag plane words (9216)
#define BUF_W (SW_W + FR_W)      // one double-buffer plane (17920 words)

// ---------------- scratch ----------------
__device__ float    g_Wh[NN * OUT_DIM];              // 8 MB
__device__ uint32_t g_Bfrag[HEADS * 512 * 32 * 32];  // 8 MB, fragment-major tf32
__device__ float    g_slT[HEADS * NN];
__device__ float    g_srT[HEADS * NN];
__device__ float    g_MT[HEADS * NN];

__device__ __forceinline__ float lrelu(float x) { return x >= 0.f ? x : 0.2f * x; }
__device__ __forceinline__ uint32_t f2tf32(float v) {
    uint32_t r;
    asm("cvt.rn.tf32.f32 %0, %1;" : "=r"(r) : "f"(v));
    return r;
}
__device__ __forceinline__ void mma1688(float* c, uint32_t a0, uint32_t a1,
                                        uint32_t a2, uint32_t a3,
                                        uint32_t b0, uint32_t b1) {
    asm volatile(
        "mma.sync.aligned.m16n8k8.row.col.f32.tf32.tf32.f32 "
        "{%0,%1,%2,%3}, {%4,%5,%6,%7}, {%8,%9}, {%0,%1,%2,%3};"
        : "+f"(c[0]), "+f"(c[1]), "+f"(c[2]), "+f"(c[3])
        : "r"(a0), "r"(a1), "r"(a2), "r"(a3), "r"(b0), "r"(b1));
}

// ---------------- Kernel A: Wh = H @ W  (fp32 tiled GEMM) ----------------
__global__ void __launch_bounds__(256) gemm_kernel(const float* __restrict__ H,
                                                   const float* __restrict__ W,
                                                   float* __restrict__ Wh) {
    __shared__ float As[16][129];
    __shared__ float Bs[16][64];
    const int t = threadIdx.x;
    const int rb = blockIdx.y * 128;
    const int cb = blockIdx.x * 64;
    const int rg = t >> 4;
    const int cg = t & 15;

    float acc[8][4];
#pragma unroll
    for (int u = 0; u < 8; u++)
#pragma unroll
        for (int v = 0; v < 4; v++) acc[u][v] = 0.f;

    for (int kb = 0; kb < IN_DIM; kb += 16) {
#pragma unroll
        for (int i = 0; i < 8; i++) {
            int idx = t + i * 256;
            int m = idx >> 4, kk = idx & 15;
            As[kk][m] = H[(size_t)(rb + m) * IN_DIM + kb + kk];
        }
#pragma unroll
        for (int i = 0; i < 4; i++) {
            int idx = t + i * 256;
            int kk = idx >> 6, c = idx & 63;
            Bs[kk][c] = W[(size_t)(kb + kk) * OUT_DIM + cb + c];
        }
        __syncthreads();
#pragma unroll
        for (int kk = 0; kk < 16; kk++) {
            float a[8], b[4];
#pragma unroll
            for (int u = 0; u < 8; u++) a[u] = As[kk][rg * 8 + u];
#pragma unroll
            for (int v = 0; v < 4; v++) b[v] = Bs[kk][cg * 4 + v];
#pragma unroll
            for (int u = 0; u < 8; u++)
#pragma unroll
                for (int v = 0; v < 4; v++) acc[u][v] = fmaf(a[u], b[v], acc[u][v]);
        }
        __syncthreads();
    }
#pragma unroll
    for (int u = 0; u < 8; u++) {
        float4 o = make_float4(acc[u][0], acc[u][1], acc[u][2], acc[u][3]);
        *reinterpret_cast<float4*>(&Wh[(size_t)(rb + rg * 8 + u) * OUT_DIM + cb + cg * 4]) = o;
    }
}

// ---------------- Kernel B: sl/sr (transposed [h][N]) ----------------
__global__ void score_kernel(const float* __restrict__ Wh,
                             const float* __restrict__ al,
                             const float* __restrict__ ar,
                             float* __restrict__ slT, float* __restrict__ srT) {
    int i = blockIdx.x;
    int h = threadIdx.x >> 5;
    int lane = threadIdx.x & 31;
    float4 w = *reinterpret_cast<const float4*>(&Wh[(size_t)i * OUT_DIM + h * DK + lane * 4]);
    float4 l = *reinterpret_cast<const float4*>(&al[h * DK + lane * 4]);
    float4 r = *reinterpret_cast<const float4*>(&ar[h * DK + lane * 4]);
    float s1 = w.x * l.x + w.y * l.y + w.z * l.z + w.w * l.w;
    float s2 = w.x * r.x + w.y * r.y + w.z * r.z + w.w * r.w;
#pragma unroll
    for (int off = 16; off > 0; off >>= 1) {
        s1 += __shfl_xor_sync(0xFFFFFFFFu, s1, off);
        s2 += __shfl_xor_sync(0xFFFFFFFFu, s2, off);
    }
    if (lane == 0) {
        slT[h * NN + i] = s1;
        srT[h * NN + i] = s2;
    }
}

// ---------------- Kernel B2: per-row masked max of sr -> M ----------------
__global__ void __launch_bounds__(256) rowmax_kernel(const int* __restrict__ A,
                                                     const float* __restrict__ slT,
                                                     const float* __restrict__ srT,
                                                     float* __restrict__ MT) {
    int i = blockIdx.x;
    int t = threadIdx.x;
    const int* arow = A + (size_t)i * NN;
    float mx[HEADS];
#pragma unroll
    for (int h = 0; h < HEADS; h++) mx[h] = -INFINITY;
    for (int j = t; j < NN; j += 256) {
        bool allowed = (arow[j] > 0) || (j == i);
        if (allowed) {
#pragma unroll
            for (int h = 0; h < HEADS; h++) mx[h] = fmaxf(mx[h], srT[h * NN + j]);
        }
    }
    __shared__ float red[HEADS][256];
#pragma unroll
    for (int h = 0; h < HEADS; h++) red[h][t] = mx[h];
    __syncthreads();
    for (int s = 128; s > 0; s >>= 1) {
        if (t < s) {
#pragma unroll
            for (int h = 0; h < HEADS; h++)
                red[h][t] = fmaxf(red[h][t], red[h][t + s]);
        }
        __syncthreads();
    }
    if (t < HEADS) {
        float e = slT[t * NN + i] + red[t][0];
        MT[t * NN + i] = lrelu(e);
    }
}

// ---------------- Kernel B3: build B fragments (tf32, mma order) ------------
// Bfrag[((h*512 + j/8)*32 + lane)*32 + word], word = nt*2 + p:
//   k = (j/8)*8 + (lane&3) + 4*p,  n = nt*8 + (lane>>2)
__global__ void __launch_bounds__(256) frag_kernel(const float* __restrict__ Wh,
                                                   uint32_t* __restrict__ Bfrag) {
    int o = blockIdx.x * 256 + threadIdx.x;   // 4*512*32*32 = 2M
    int word = o & 31;
    int lane = (o >> 5) & 31;
    int jb8  = (o >> 10) & 511;
    int h    = o >> 19;
    int j = jb8 * 8 + (lane & 3) + 4 * (word & 1);
    int n = (word >> 1) * 8 + (lane >> 2);
    float v = Wh[(size_t)j * OUT_DIM + h * DK + n];
    Bfrag[o] = f2tf32(v);
}

// ---------------- Kernel C: mma.sync tf32 masked-softmax aggregation -------
// grid (32, HEADS), 256 threads (8 warps). CTA = 128 rows, one head.
// j tiles of 64, double-buffered smem, 1 sync/tile.
__global__ void __launch_bounds__(256) attn_kernel(const int* __restrict__ A,
                                                   const uint32_t* __restrict__ Bfrag,
                                                   const float* __restrict__ slT,
                                                   const float* __restrict__ srT,
                                                   const float* __restrict__ MT,
                                                   float* __restrict__ out) {
    extern __shared__ uint32_t dyn[];
    __shared__ float ssl[128], sMx[128];

    const int h = blockIdx.y;
    const int rb = blockIdx.x * 128;
    const int t = threadIdx.x;
    const int wid = t >> 5, lane = t & 31;
    const int g = lane >> 2, tig = lane & 3;

    if (t < 128) {
        ssl[t] = slT[h * NN + rb + t];
        sMx[t] = MT[h * NN + rb + t];
    }
    __syncthreads();

    float acc[16][4];
#pragma unroll
    for (int nt = 0; nt < 16; nt++)
#pragma unroll
        for (int v = 0; v < 4; v++) acc[nt][v] = 0.f;
    float ls0 = 0.f, ls1 = 0.f;

    const int c1 = t & 63;        // phase-1 column
    const int r0 = t >> 6;        // phase-1 base row (stride 4)
    const int arow_a = (wid * 16 + g) * SW_PAD;
    const int arow_b = arow_a + 8 * SW_PAD;
    const float4* Bfrag4 = reinterpret_cast<const float4*>(Bfrag);

    for (int jt = 0; jt < NN / KT; jt++) {
        const int jb = jt * KT;
        const int buf = jt & 1;
        uint32_t* sw    = dyn + buf * BUF_W;
        uint32_t* sfrag = sw + SW_W;

        // ---- fill: weights (tf32) ----
        float srv = srT[h * NN + jb + c1];
#pragma unroll
        for (int k = 0; k < 32; k++) {
            int r = r0 + k * 4;
            int gi = rb + r, gj = jb + c1;
            int a = A[(size_t)gi * NN + gj];
            float e = lrelu(ssl[r] + srv);
            float w = ((a > 0) | (gi == gj)) ? __expf(e - sMx[r]) : 0.f;
            sw[r * SW_PAD + c1] = f2tf32(w);
        }
        // ---- fill: B fragments (coalesced float4, 8 per thread) ----
#pragma unroll
        for (int i = 0; i < 8; i++) {
            int flat = t + i * 256;            // 2048 float4
            int w4 = flat & 7;
            int ln = (flat >> 3) & 31;
            int kc = flat >> 8;
            float4 v = Bfrag4[((size_t)(h * 512 + jt * 8 + kc) * 32 + ln) * 8 + w4];
            *reinterpret_cast<float4*>(sfrag + (kc * 32 + ln) * FR_PAD + w4 * 4) = v;
        }
        __syncthreads();

        // ---- mma: 8 k-chunks of 8 ----
#pragma unroll
        for (int kc = 0; kc < 8; kc++) {
            const int k0 = kc * 8 + tig;
            uint32_t a0 = sw[arow_a + k0];
            uint32_t a2 = sw[arow_a + k0 + 4];
            uint32_t a1 = sw[arow_b + k0];
            uint32_t a3 = sw[arow_b + k0 + 4];
            ls0 += __uint_as_float(a0) + __uint_as_float(a2);
            ls1 += __uint_as_float(a1) + __uint_as_float(a3);
            const float4* bp = reinterpret_cast<const float4*>(sfrag + (kc * 32 + lane) * FR_PAD);
#pragma unroll
            for (int i = 0; i < 8; i++) {
                float4 b = bp[i];
                mma1688(acc[2 * i], a0, a1, a2, a3,
                        __float_as_uint(b.x), __float_as_uint(b.y));
                mma1688(acc[2 * i + 1], a0, a1, a2, a3,
                        __float_as_uint(b.z), __float_as_uint(b.w));
            }
        }
    }

    // ---- reduce lsum across the quad ----
    ls0 += __shfl_xor_sync(0xFFFFFFFFu, ls0, 1);
    ls0 += __shfl_xor_sync(0xFFFFFFFFu, ls0, 2);
    ls1 += __shfl_xor_sync(0xFFFFFFFFu, ls1, 1);
    ls1 += __shfl_xor_sync(0xFFFFFFFFu, ls1, 2);
    float inv0 = 1.f / ls0, inv1 = 1.f / ls1;

    // ---- epilogue: normalize + ELU, float2 stores ----
    const int row0 = rb + wid * 16 + g;
    const int row1 = row0 + 8;
#pragma unroll
    for (int nt = 0; nt < 16; nt++) {
        int col = h * DK + nt * 8 + 2 * tig;
        float x0 = acc[nt][0] * inv0, x1 = acc[nt][1] * inv0;
        float y0 = acc[nt][2] * inv1, y1 = acc[nt][3] * inv1;
        float2 o0, o1;
        o0.x = x0 > 0.f ? x0 : (__expf(x0) - 1.f);
        o0.y = x1 > 0.f ? x1 : (__expf(x1) - 1.f);
        o1.x = y0 > 0.f ? y0 : (__expf(y0) - 1.f);
        o1.y = y1 > 0.f ? y1 : (__expf(y1) - 1.f);
        *reinterpret_cast<float2*>(&out[(size_t)row0 * OUT_DIM + col]) = o0;
        *reinterpret_cast<float2*>(&out[(size_t)row1 * OUT_DIM + col]) = o1;
    }
}

// ---------------- launch ----------------
extern "C" void kernel_launch(void* const* d_in, const int* in_sizes, int n_in,
                              void* d_out, int out_size) {
    const float* H  = (const float*)d_in[0];
    const int*   A  = (const int*)  d_in[1];
    const float* W  = (const float*)d_in[2];
    const float* al = (const float*)d_in[3];
    const float* ar = (const float*)d_in[4];
    float* out = (float*)d_out;

    float*    Wh;    cudaGetSymbolAddress((void**)&Wh,    g_Wh);
    uint32_t* Bfrag; cudaGetSymbolAddress((void**)&Bfrag, g_Bfrag);
    float*    slT;   cudaGetSymbolAddress((void**)&slT,   g_slT);
    float*    srT;   cudaGetSymbolAddress((void**)&srT,   g_srT);
    float*    MT;    cudaGetSymbolAddress((void**)&MT,    g_MT);

    dim3 gA(OUT_DIM / 64, NN / 128);
    gemm_kernel<<<gA, 256>>>(H, W, Wh);

    score_kernel<<<NN, 128>>>(Wh, al, ar, slT, srT);

    rowmax_kernel<<<NN, 256>>>(A, slT, srT, MT);

    frag_kernel<<<(HEADS * 512 * 32 * 32) / 256, 256>>>(Wh, Bfrag);

    const int dyn_bytes = 2 * BUF_W * 4;   // 143360
    cudaFuncSetAttribute(attn_kernel, cudaFuncAttributeMaxDynamicSharedMemorySize, dyn_bytes);
    dim3 gC(NN / 128, HEADS);
    attn_kernel<<<gC, 256, dyn_bytes>>>(A, Bfrag, slT, srT, MT, out);
}

// round 5
// speedup vs baseline: 1.6685x; 1.6685x over previous
#include <cuda_runtime.h>
#include <cuda_bf16.h>
#include <math.h>
#include <stdint.h>

#define NN 4096
#define IN_DIM 512
#define OUT_DIM 512
#define HEADS 4
#define DK 128
#define KT 64                    // j-tile
#define PAD 68                   // smem row stride (words): frag LDS conflict-free
#define SW_W (128 * PAD)         // weight plane words
#define WH_W (128 * PAD)         // WhT plane words
#define BUF_W (SW_W + WH_W)      // one double-buffer plane

// ---------------- scratch ----------------
__device__ float    g_Wh[NN * OUT_DIM];       // 8 MB
__device__ float    g_WhT[OUT_DIM * NN];      // 8 MB, [d'][j], tf32-rounded
__device__ uint32_t g_Amask[NN * (NN / 32)];  // 2 MB packed adjacency
__device__ float    g_slT[HEADS * NN];
__device__ float    g_srT[HEADS * NN];
__device__ float    g_MT[HEADS * NN];

__device__ __forceinline__ float lrelu(float x) { return x >= 0.f ? x : 0.2f * x; }
__device__ __forceinline__ uint32_t f2tf32(float v) {
    uint32_t r;
    asm("cvt.rn.tf32.f32 %0, %1;" : "=r"(r) : "f"(v));
    return r;
}
__device__ __forceinline__ void mma1688(float* c, uint32_t a0, uint32_t a1,
                                        uint32_t a2, uint32_t a3,
                                        uint32_t b0, uint32_t b1) {
    asm volatile(
        "mma.sync.aligned.m16n8k8.row.col.f32.tf32.tf32.f32 "
        "{%0,%1,%2,%3}, {%4,%5,%6,%7}, {%8,%9}, {%0,%1,%2,%3};"
        : "+f"(c[0]), "+f"(c[1]), "+f"(c[2]), "+f"(c[3])
        : "r"(a0), "r"(a1), "r"(a2), "r"(a3), "r"(b0), "r"(b1));
}

// ---------------- Kernel A: Wh = H @ W, fused WhT(tf32) epilogue ------------
__global__ void __launch_bounds__(256) gemm_kernel(const float* __restrict__ H,
                                                   const float* __restrict__ W,
                                                   float* __restrict__ Wh,
                                                   float* __restrict__ WhT) {
    __shared__ float As[16][129];
    __shared__ float Bs[16][64];
    const int t = threadIdx.x;
    const int rb = blockIdx.y * 128;
    const int cb = blockIdx.x * 64;
    const int rg = t >> 4;
    const int cg = t & 15;

    float acc[8][4];
#pragma unroll
    for (int u = 0; u < 8; u++)
#pragma unroll
        for (int v = 0; v < 4; v++) acc[u][v] = 0.f;

    for (int kb = 0; kb < IN_DIM; kb += 16) {
#pragma unroll
        for (int i = 0; i < 8; i++) {
            int idx = t + i * 256;
            int m = idx >> 4, kk = idx & 15;
            As[kk][m] = H[(size_t)(rb + m) * IN_DIM + kb + kk];
        }
#pragma unroll
        for (int i = 0; i < 4; i++) {
            int idx = t + i * 256;
            int kk = idx >> 6, c = idx & 63;
            Bs[kk][c] = W[(size_t)(kb + kk) * OUT_DIM + cb + c];
        }
        __syncthreads();
#pragma unroll
        for (int kk = 0; kk < 16; kk++) {
            float a[8], b[4];
#pragma unroll
            for (int u = 0; u < 8; u++) a[u] = As[kk][rg * 8 + u];
#pragma unroll
            for (int v = 0; v < 4; v++) b[v] = Bs[kk][cg * 4 + v];
#pragma unroll
            for (int u = 0; u < 8; u++)
#pragma unroll
                for (int v = 0; v < 4; v++) acc[u][v] = fmaf(a[u], b[v], acc[u][v]);
        }
        __syncthreads();
    }
    // Wh rows, coalesced
#pragma unroll
    for (int u = 0; u < 8; u++) {
        float4 o = make_float4(acc[u][0], acc[u][1], acc[u][2], acc[u][3]);
        *reinterpret_cast<float4*>(&Wh[(size_t)(rb + rg * 8 + u) * OUT_DIM + cb + cg * 4]) = o;
    }
    // WhT[d][j] tf32, per-thread 8 consecutive j
#pragma unroll
    for (int v = 0; v < 4; v++) {
        int d = cb + cg * 4 + v;
        float4 lo, hi;
        lo.x = __uint_as_float(f2tf32(acc[0][v]));
        lo.y = __uint_as_float(f2tf32(acc[1][v]));
        lo.z = __uint_as_float(f2tf32(acc[2][v]));
        lo.w = __uint_as_float(f2tf32(acc[3][v]));
        hi.x = __uint_as_float(f2tf32(acc[4][v]));
        hi.y = __uint_as_float(f2tf32(acc[5][v]));
        hi.z = __uint_as_float(f2tf32(acc[6][v]));
        hi.w = __uint_as_float(f2tf32(acc[7][v]));
        float4* dst = reinterpret_cast<float4*>(&WhT[(size_t)d * NN + rb + rg * 8]);
        dst[0] = lo;
        dst[1] = hi;
    }
}

// ---------------- Kernel B: sl/sr (transposed [h][N]) ----------------
__global__ void score_kernel(const float* __restrict__ Wh,
                             const float* __restrict__ al,
                             const float* __restrict__ ar,
                             float* __restrict__ slT, float* __restrict__ srT) {
    int i = blockIdx.x;
    int h = threadIdx.x >> 5;
    int lane = threadIdx.x & 31;
    float4 w = *reinterpret_cast<const float4*>(&Wh[(size_t)i * OUT_DIM + h * DK + lane * 4]);
    float4 l = *reinterpret_cast<const float4*>(&al[h * DK + lane * 4]);
    float4 r = *reinterpret_cast<const float4*>(&ar[h * DK + lane * 4]);
    float s1 = w.x * l.x + w.y * l.y + w.z * l.z + w.w * l.w;
    float s2 = w.x * r.x + w.y * r.y + w.z * r.z + w.w * r.w;
#pragma unroll
    for (int off = 16; off > 0; off >>= 1) {
        s1 += __shfl_xor_sync(0xFFFFFFFFu, s1, off);
        s2 += __shfl_xor_sync(0xFFFFFFFFu, s2, off);
    }
    if (lane == 0) {
        slT[h * NN + i] = s1;
        srT[h * NN + i] = s2;
    }
}

// ---------------- Kernel B2: masked row-max + packed adjacency bitmask ------
__global__ void __launch_bounds__(256) rowmax_kernel(const int* __restrict__ A,
                                                     const float* __restrict__ slT,
                                                     const float* __restrict__ srT,
                                                     float* __restrict__ MT,
                                                     uint32_t* __restrict__ Amask) {
    int i = blockIdx.x;
    int t = threadIdx.x;
    int w = t >> 5, lane = t & 31;
    const int* arow = A + (size_t)i * NN;
    float mx[HEADS];
#pragma unroll
    for (int h = 0; h < HEADS; h++) mx[h] = -INFINITY;
    for (int it = 0; it < NN / 256; it++) {
        int j = it * 256 + t;
        bool edge = arow[j] > 0;
        uint32_t bits = __ballot_sync(0xFFFFFFFFu, edge);
        if (lane == 0) Amask[i * (NN / 32) + it * 8 + w] = bits;
        if (edge || (j == i)) {
#pragma unroll
            for (int h = 0; h < HEADS; h++) mx[h] = fmaxf(mx[h], srT[h * NN + j]);
        }
    }
    __shared__ float red[HEADS][256];
#pragma unroll
    for (int h = 0; h < HEADS; h++) red[h][t] = mx[h];
    __syncthreads();
    for (int s = 128; s > 0; s >>= 1) {
        if (t < s) {
#pragma unroll
            for (int h = 0; h < HEADS; h++)
                red[h][t] = fmaxf(red[h][t], red[h][t + s]);
        }
        __syncthreads();
    }
    if (t < HEADS) {
        float e = slT[t * NN + i] + red[t][0];
        MT[t * NN + i] = lrelu(e);
    }
}

// ---------------- Kernel C: mma.sync tf32 masked-softmax aggregation -------
// grid (32, HEADS), 512 threads (16 warps). CTA = 128 rows, one head.
// Warp = 16 rows x 64 dims. j tiles of 64, double-buffered, 1 sync/tile.
__global__ void __launch_bounds__(512) attn_kernel(const uint32_t* __restrict__ Amask,
                                                   const float* __restrict__ WhT,
                                                   const float* __restrict__ slT,
                                                   const float* __restrict__ srT,
                                                   const float* __restrict__ MT,
                                                   float* __restrict__ out) {
    extern __shared__ uint32_t dyn[];
    __shared__ float ssl[128], sMx[128];

    const int h = blockIdx.y;
    const int rb = blockIdx.x * 128;
    const int t = threadIdx.x;
    const int wid = t >> 5, lane = t & 31;
    const int g = lane >> 2, tig = lane & 3;
    const int rg = wid >> 1;         // 16-row group 0..7
    const int ch = wid & 1;          // 64-dim half

    if (t < 128) {
        ssl[t] = slT[h * NN + rb + t];
        sMx[t] = MT[h * NN + rb + t];
    }
    __syncthreads();

    float acc[8][4];
#pragma unroll
    for (int nt = 0; nt < 8; nt++)
#pragma unroll
        for (int v = 0; v < 4; v++) acc[nt][v] = 0.f;
    float ls0 = 0.f, ls1 = 0.f;

    const int c1 = t & 63;           // fill column
    const int r0 = t >> 6;           // fill base row (stride 8)
    const int arow_a = (rg * 16 + g) * PAD;
    const int arow_b = arow_a + 8 * PAD;
    const int nbase = ch * 64;
    const float4* WhT4 = reinterpret_cast<const float4*>(WhT);

    for (int jt = 0; jt < NN / KT; jt++) {
        const int jb = jt * KT;
        const int buf = jt & 1;
        uint32_t* sw  = dyn + buf * BUF_W;
        float*    swh = reinterpret_cast<float*>(sw + SW_W);

        // ---- fill: weights via packed mask (tf32) ----
        float srv = srT[h * NN + jb + c1];
        const int mword = (jb >> 5) + (c1 >> 5);
        const uint32_t mbit = 1u << (c1 & 31);
#pragma unroll
        for (int k = 0; k < 16; k++) {
            int r = r0 + k * 8;
            int gi = rb + r;
            uint32_t m = Amask[gi * (NN / 32) + mword];
            bool allowed = (m & mbit) || (gi == jb + c1);
            float e = lrelu(ssl[r] + srv);
            float w = allowed ? __expf(e - sMx[r]) : 0.f;
            sw[r * PAD + c1] = f2tf32(w);
        }
        // ---- fill: WhT tile (128 d x 64 j), float4 coalesced ----
#pragma unroll
        for (int i = 0; i < 4; i++) {
            int flat = t + i * 512;           // 2048 float4
            int d = flat >> 4, j4 = flat & 15;
            float4 v = WhT4[(size_t)(h * DK + d) * (NN / 4) + jt * 16 + j4];
            *reinterpret_cast<float4*>(swh + d * PAD + j4 * 4) = v;
        }
        __syncthreads();

        // ---- mma: 8 k-chunks of 8 ----
#pragma unroll
        for (int kc = 0; kc < 8; kc++) {
            const int k0 = kc * 8 + tig;
            uint32_t a0 = sw[arow_a + k0];
            uint32_t a2 = sw[arow_a + k0 + 4];
            uint32_t a1 = sw[arow_b + k0];
            uint32_t a3 = sw[arow_b + k0 + 4];
            ls0 += __uint_as_float(a0) + __uint_as_float(a2);
            ls1 += __uint_as_float(a1) + __uint_as_float(a3);
#pragma unroll
            for (int nt = 0; nt < 8; nt++) {
                uint32_t b0 = __float_as_uint(swh[(nbase + nt * 8 + g) * PAD + k0]);
                uint32_t b1 = __float_as_uint(swh[(nbase + nt * 8 + g) * PAD + k0 + 4]);
                mma1688(acc[nt], a0, a1, a2, a3, b0, b1);
            }
        }
    }

    // ---- reduce lsum across the quad ----
    ls0 += __shfl_xor_sync(0xFFFFFFFFu, ls0, 1);
    ls0 += __shfl_xor_sync(0xFFFFFFFFu, ls0, 2);
    ls1 += __shfl_xor_sync(0xFFFFFFFFu, ls1, 1);
    ls1 += __shfl_xor_sync(0xFFFFFFFFu, ls1, 2);
    float inv0 = 1.f / ls0, inv1 = 1.f / ls1;

    // ---- epilogue: normalize + ELU, float2 stores ----
    const int row0 = rb + rg * 16 + g;
    const int row1 = row0 + 8;
#pragma unroll
    for (int nt = 0; nt < 8; nt++) {
        int col = h * DK + nbase + nt * 8 + 2 * tig;
        float x0 = acc[nt][0] * inv0, x1 = acc[nt][1] * inv0;
        float y0 = acc[nt][2] * inv1, y1 = acc[nt][3] * inv1;
        float2 o0, o1;
        o0.x = x0 > 0.f ? x0 : (__expf(x0) - 1.f);
        o0.y = x1 > 0.f ? x1 : (__expf(x1) - 1.f);
        o1.x = y0 > 0.f ? y0 : (__expf(y0) - 1.f);
        o1.y = y1 > 0.f ? y1 : (__expf(y1) - 1.f);
        *reinterpret_cast<float2*>(&out[(size_t)row0 * OUT_DIM + col]) = o0;
        *reinterpret_cast<float2*>(&out[(size_t)row1 * OUT_DIM + col]) = o1;
    }
}

// ---------------- launch ----------------
extern "C" void kernel_launch(void* const* d_in, const int* in_sizes, int n_in,
                              void* d_out, int out_size) {
    const float* H  = (const float*)d_in[0];
    const int*   A  = (const int*)  d_in[1];
    const float* W  = (const float*)d_in[2];
    const float* al = (const float*)d_in[3];
    const float* ar = (const float*)d_in[4];
    float* out = (float*)d_out;

    float*    Wh;    cudaGetSymbolAddress((void**)&Wh,    g_Wh);
    float*    WhT;   cudaGetSymbolAddress((void**)&WhT,   g_WhT);
    uint32_t* Amask; cudaGetSymbolAddress((void**)&Amask, g_Amask);
    float*    slT;   cudaGetSymbolAddress((void**)&slT,   g_slT);
    float*    srT;   cudaGetSymbolAddress((void**)&srT,   g_srT);
    float*    MT;    cudaGetSymbolAddress((void**)&MT,    g_MT);

    dim3 gA(OUT_DIM / 64, NN / 128);
    gemm_kernel<<<gA, 256>>>(H, W, Wh, WhT);

    score_kernel<<<NN, 128>>>(Wh, al, ar, slT, srT);

    rowmax_kernel<<<NN, 256>>>(A, slT, srT, MT, Amask);

    const int dyn_bytes = 2 * BUF_W * 4;   // 139264
    cudaFuncSetAttribute(attn_kernel, cudaFuncAttributeMaxDynamicSharedMemorySize, dyn_bytes);
    dim3 gC(NN / 128, HEADS);
    attn_kernel<<<gC, 512, dyn_bytes>>>(Amask, WhT, slT, srT, MT, out);
}

// round 7
// speedup vs baseline: 1.7162x; 1.0286x over previous
#include <cuda_runtime.h>
#include <cuda_bf16.h>
#include <math.h>
#include <stdint.h>

#define NN 4096
#define IN_DIM 512
#define OUT_DIM 512
#define HEADS 4
#define DK 128
#define KT 64                    // j-tile
#define PAD 68                   // smem row stride (words)
#define SW_W (64 * PAD)          // weight plane words (4352)
#define WH_W (128 * PAD)         // WhT plane words (8704)
#define BUF_W (SW_W + WH_W)      // one double-buffer plane (13056)

// ---------------- scratch ----------------
__device__ float    g_Wh[NN * OUT_DIM];       // 8 MB
__device__ float    g_WhT[OUT_DIM * NN];      // 8 MB, [d'][j], tf32-rounded
__device__ uint32_t g_Amask[NN * (NN / 32)];  // 2 MB packed adjacency
__device__ float    g_slT[HEADS * NN];
__device__ float    g_srT[HEADS * NN];
__device__ float    g_MT[HEADS * NN];

__device__ __forceinline__ float lrelu(float x) { return x >= 0.f ? x : 0.2f * x; }
__device__ __forceinline__ uint32_t f2tf32(float v) {
    uint32_t r;
    asm("cvt.rn.tf32.f32 %0, %1;" : "=r"(r) : "f"(v));
    return r;
}
__device__ __forceinline__ void mma1688(float* c, uint32_t a0, uint32_t a1,
                                        uint32_t a2, uint32_t a3,
                                        uint32_t b0, uint32_t b1) {
    asm volatile(
        "mma.sync.aligned.m16n8k8.row.col.f32.tf32.tf32.f32 "
        "{%0,%1,%2,%3}, {%4,%5,%6,%7}, {%8,%9}, {%0,%1,%2,%3};"
        : "+f"(c[0]), "+f"(c[1]), "+f"(c[2]), "+f"(c[3])
        : "r"(a0), "r"(a1), "r"(a2), "r"(a3), "r"(b0), "r"(b1));
}

// ---------------- Kernel A: Wh = H @ W, fused WhT(tf32) epilogue ------------
__global__ void __launch_bounds__(256) gemm_kernel(const float* __restrict__ H,
                                                   const float* __restrict__ W,
                                                   float* __restrict__ Wh,
                                                   float* __restrict__ WhT) {
    __shared__ float As[16][129];
    __shared__ float Bs[16][64];
    const int t = threadIdx.x;
    const int rb = blockIdx.y * 128;
    const int cb = blockIdx.x * 64;
    const int rg = t >> 4;
    const int cg = t & 15;

    float acc[8][4];
#pragma unroll
    for (int u = 0; u < 8; u++)
#pragma unroll
        for (int v = 0; v < 4; v++) acc[u][v] = 0.f;

    for (int kb = 0; kb < IN_DIM; kb += 16) {
#pragma unroll
        for (int i = 0; i < 8; i++) {
            int idx = t + i * 256;
            int m = idx >> 4, kk = idx & 15;
            As[kk][m] = H[(size_t)(rb + m) * IN_DIM + kb + kk];
        }
#pragma unroll
        for (int i = 0; i < 4; i++) {
            int idx = t + i * 256;
            int kk = idx >> 6, c = idx & 63;
            Bs[kk][c] = W[(size_t)(kb + kk) * OUT_DIM + cb + c];
        }
        __syncthreads();
#pragma unroll
        for (int kk = 0; kk < 16; kk++) {
            float a[8], b[4];
#pragma unroll
            for (int u = 0; u < 8; u++) a[u] = As[kk][rg * 8 + u];
#pragma unroll
            for (int v = 0; v < 4; v++) b[v] = Bs[kk][cg * 4 + v];
#pragma unroll
            for (int u = 0; u < 8; u++)
#pragma unroll
                for (int v = 0; v < 4; v++) acc[u][v] = fmaf(a[u], b[v], acc[u][v]);
        }
        __syncthreads();
    }
#pragma unroll
    for (int u = 0; u < 8; u++) {
        float4 o = make_float4(acc[u][0], acc[u][1], acc[u][2], acc[u][3]);
        *reinterpret_cast<float4*>(&Wh[(size_t)(rb + rg * 8 + u) * OUT_DIM + cb + cg * 4]) = o;
    }
#pragma unroll
    for (int v = 0; v < 4; v++) {
        int d = cb + cg * 4 + v;
        float4 lo, hi;
        lo.x = __uint_as_float(f2tf32(acc[0][v]));
        lo.y = __uint_as_float(f2tf32(acc[1][v]));
        lo.z = __uint_as_float(f2tf32(acc[2][v]));
        lo.w = __uint_as_float(f2tf32(acc[3][v]));
        hi.x = __uint_as_float(f2tf32(acc[4][v]));
        hi.y = __uint_as_float(f2tf32(acc[5][v]));
        hi.z = __uint_as_float(f2tf32(acc[6][v]));
        hi.w = __uint_as_float(f2tf32(acc[7][v]));
        float4* dst = reinterpret_cast<float4*>(&WhT[(size_t)d * NN + rb + rg * 8]);
        dst[0] = lo;
        dst[1] = hi;
    }
}

// ---------------- Kernel B: sl/sr (transposed [h][N]) ----------------
__global__ void score_kernel(const float* __restrict__ Wh,
                             const float* __restrict__ al,
                             const float* __restrict__ ar,
                             float* __restrict__ slT, float* __restrict__ srT) {
    int i = blockIdx.x;
    int h = threadIdx.x >> 5;
    int lane = threadIdx.x & 31;
    float4 w = *reinterpret_cast<const float4*>(&Wh[(size_t)i * OUT_DIM + h * DK + lane * 4]);
    float4 l = *reinterpret_cast<const float4*>(&al[h * DK + lane * 4]);
    float4 r = *reinterpret_cast<const float4*>(&ar[h * DK + lane * 4]);
    float s1 = w.x * l.x + w.y * l.y + w.z * l.z + w.w * l.w;
    float s2 = w.x * r.x + w.y * r.y + w.z * r.z + w.w * r.w;
#pragma unroll
    for (int off = 16; off > 0; off >>= 1) {
        s1 += __shfl_xor_sync(0xFFFFFFFFu, s1, off);
        s2 += __shfl_xor_sync(0xFFFFFFFFu, s2, off);
    }
    if (lane == 0) {
        slT[h * NN + i] = s1;
        srT[h * NN + i] = s2;
    }
}

// ---------------- Kernel B2: masked row-max + packed adjacency bitmask ------
__global__ void __launch_bounds__(256) rowmax_kernel(const int* __restrict__ A,
                                                     const float* __restrict__ slT,
                                                     const float* __restrict__ srT,
                                                     float* __restrict__ MT,
                                                     uint32_t* __restrict__ Amask) {
    int i = blockIdx.x;
    int t = threadIdx.x;
    int w = t >> 5, lane = t & 31;
    const int* arow = A + (size_t)i * NN;
    float mx[HEADS];
#pragma unroll
    for (int h = 0; h < HEADS; h++) mx[h] = -INFINITY;
    for (int it = 0; it < NN / 256; it++) {
        int j = it * 256 + t;
        bool edge = arow[j] > 0;
        uint32_t bits = __ballot_sync(0xFFFFFFFFu, edge);
        if (lane == 0) Amask[i * (NN / 32) + it * 8 + w] = bits;
        if (edge || (j == i)) {
#pragma unroll
            for (int h = 0; h < HEADS; h++) mx[h] = fmaxf(mx[h], srT[h * NN + j]);
        }
    }
    __shared__ float red[HEADS][256];
#pragma unroll
    for (int h = 0; h < HEADS; h++) red[h][t] = mx[h];
    __syncthreads();
    for (int s = 128; s > 0; s >>= 1) {
        if (t < s) {
#pragma unroll
            for (int h = 0; h < HEADS; h++)
                red[h][t] = fmaxf(red[h][t], red[h][t + s]);
        }
        __syncthreads();
    }
    if (t < HEADS) {
        float e = slT[t * NN + i] + red[t][0];
        MT[t * NN + i] = lrelu(e);
    }
}

// ---------------- Kernel C: mma.sync tf32 masked-softmax aggregation -------
// grid (64, HEADS), 256 threads (8 warps), 2 CTAs/SM. CTA = 64 rows, one head.
// Warp = 16 rows x 64 dims. j tiles of 64, double-buffered, register-pipelined.
__global__ void __launch_bounds__(256, 2) attn_kernel(const uint32_t* __restrict__ Amask,
                                                      const float* __restrict__ WhT,
                                                      const float* __restrict__ slT,
                                                      const float* __restrict__ srT,
                                                      const float* __restrict__ MT,
                                                      float* __restrict__ out) {
    extern __shared__ uint32_t dyn[];
    __shared__ float ssl[64], sMx[64];

    const int h = blockIdx.y;
    const int rb = blockIdx.x * 64;
    const int t = threadIdx.x;
    const int wid = t >> 5, lane = t & 31;
    const int g = lane >> 2, tig = lane & 3;
    const int rg = wid >> 1;          // 16-row group 0..3
    const int ch = wid & 1;           // 64-dim half

    if (t < 64) {
        ssl[t] = slT[h * NN + rb + t];
        sMx[t] = MT[h * NN + rb + t];
    }
    __syncthreads();

    // fill mapping: thread -> 1 row x 16 cols
    const int fr = t >> 2;            // row 0..63
    const int fc = (t & 3) * 16;      // col base
    const int gi = rb + fr;
    const float slv = ssl[fr], smv = sMx[fr];
    const float4* WhT4 = reinterpret_cast<const float4*>(WhT);
    const float4* srT4 = reinterpret_cast<const float4*>(srT + (size_t)h * NN);

    float acc[8][4];
#pragma unroll
    for (int nt = 0; nt < 8; nt++)
#pragma unroll
        for (int v = 0; v < 4; v++) acc[nt][v] = 0.f;
    float ls0 = 0.f, ls1 = 0.f;

    const int arow_a = (rg * 16 + g) * PAD;
    const int arow_b = arow_a + 8 * PAD;
    const int nbase = ch * 64;

    // prefetch registers
    uint32_t mraw;
    float4 sr4[4];
    float4 wh[8];

    // ---- prefetch + store tile 0 ----
    {
        const int jb = 0;
        mraw = Amask[(size_t)gi * (NN / 32) + ((jb + fc) >> 5)];
#pragma unroll
        for (int u = 0; u < 4; u++) sr4[u] = srT4[(jb + fc) / 4 + u];
#pragma unroll
        for (int i = 0; i < 8; i++) {
            int flat = t + i * 256;
            int d = flat >> 4, j4 = flat & 15;
            wh[i] = WhT4[(size_t)(h * DK + d) * (NN / 4) + (jb >> 2) + j4];
        }
        uint32_t* sw = dyn;
        float* swh = reinterpret_cast<float*>(sw + SW_W);
        uint32_t mb = (fc & 16) ? (mraw >> 16) : mraw;
        const float* srv = reinterpret_cast<const float*>(sr4);
#pragma unroll
        for (int q = 0; q < 4; q++) {
            uint4 pk;
            float e0, w0;
#pragma unroll
            for (int u = 0; u < 4; u++) {
                int uu = q * 4 + u;
                int gj = jb + fc + uu;
                bool allowed = ((mb >> uu) & 1u) || (gi == gj);
                e0 = lrelu(slv + srv[uu]);
                w0 = allowed ? __expf(e0 - smv) : 0.f;
                reinterpret_cast<uint32_t*>(&pk)[u] = f2tf32(w0);
            }
            *reinterpret_cast<uint4*>(sw + fr * PAD + fc + q * 4) = pk;
        }
#pragma unroll
        for (int i = 0; i < 8; i++) {
            int flat = t + i * 256;
            int d = flat >> 4, j4 = flat & 15;
            *reinterpret_cast<float4*>(swh + d * PAD + j4 * 4) = wh[i];
        }
    }
    __syncthreads();

    for (int jt = 0; jt < NN / KT; jt++) {
        // ---- prefetch tile jt+1 into registers (hidden behind MMA) ----
        if (jt + 1 < NN / KT) {
            const int jb = (jt + 1) * KT;
            mraw = Amask[(size_t)gi * (NN / 32) + ((jb + fc) >> 5)];
#pragma unroll
            for (int u = 0; u < 4; u++) sr4[u] = srT4[(jb + fc) / 4 + u];
#pragma unroll
            for (int i = 0; i < 8; i++) {
                int flat = t + i * 256;
                int d = flat >> 4, j4 = flat & 15;
                wh[i] = WhT4[(size_t)(h * DK + d) * (NN / 4) + (jb >> 2) + j4];
            }
        }

        // ---- mma phase on buffer jt&1 ----
        {
            uint32_t* sw = dyn + (jt & 1) * BUF_W;
            float* swh = reinterpret_cast<float*>(sw + SW_W);
#pragma unroll
            for (int kc = 0; kc < 8; kc++) {
                const int k0 = kc * 8 + tig;
                uint32_t a0 = sw[arow_a + k0];
                uint32_t a2 = sw[arow_a + k0 + 4];
                uint32_t a1 = sw[arow_b + k0];
                uint32_t a3 = sw[arow_b + k0 + 4];
                ls0 += __uint_as_float(a0) + __uint_as_float(a2);
                ls1 += __uint_as_float(a1) + __uint_as_float(a3);
#pragma unroll
                for (int nt = 0; nt < 8; nt++) {
                    uint32_t b0 = __float_as_uint(swh[(nbase + nt * 8 + g) * PAD + k0]);
                    uint32_t b1 = __float_as_uint(swh[(nbase + nt * 8 + g) * PAD + k0 + 4]);
                    mma1688(acc[nt], a0, a1, a2, a3, b0, b1);
                }
            }
        }

        // ---- store tile jt+1 into buffer (jt+1)&1 ----
        if (jt + 1 < NN / KT) {
            const int jb = (jt + 1) * KT;
            uint32_t* sw = dyn + ((jt + 1) & 1) * BUF_W;
            float* swh = reinterpret_cast<float*>(sw + SW_W);
            uint32_t mb = (fc & 16) ? (mraw >> 16) : mraw;
            const float* srv = reinterpret_cast<const float*>(sr4);
#pragma unroll
            for (int q = 0; q < 4; q++) {
                uint4 pk;
#pragma unroll
                for (int u = 0; u < 4; u++) {
                    int uu = q * 4 + u;
                    int gj = jb + fc + uu;
                    bool allowed = ((mb >> uu) & 1u) || (gi == gj);
                    float e = lrelu(slv + srv[uu]);
                    float w = allowed ? __expf(e - smv) : 0.f;
                    reinterpret_cast<uint32_t*>(&pk)[u] = f2tf32(w);
                }
                *reinterpret_cast<uint4*>(sw + fr * PAD + fc + q * 4) = pk;
            }
#pragma unroll
            for (int i = 0; i < 8; i++) {
                int flat = t + i * 256;
                int d = flat >> 4, j4 = flat & 15;
                *reinterpret_cast<float4*>(swh + d * PAD + j4 * 4) = wh[i];
            }
        }
        __syncthreads();
    }

    // ---- reduce lsum across the quad ----
    ls0 += __shfl_xor_sync(0xFFFFFFFFu, ls0, 1);
    ls0 += __shfl_xor_sync(0xFFFFFFFFu, ls0, 2);
    ls1 += __shfl_xor_sync(0xFFFFFFFFu, ls1, 1);
    ls1 += __shfl_xor_sync(0xFFFFFFFFu, ls1, 2);
    float inv0 = 1.f / ls0, inv1 = 1.f / ls1;

    // ---- epilogue: normalize + ELU, float2 stores ----
    const int row0 = rb + rg * 16 + g;
    const int row1 = row0 + 8;
#pragma unroll
    for (int nt = 0; nt < 8; nt++) {
        int col = h * DK + nbase + nt * 8 + 2 * tig;
        float x0 = acc[nt][0] * inv0, x1 = acc[nt][1] * inv0;
        float y0 = acc[nt][2] * inv1, y1 = acc[nt][3] * inv1;
        float2 o0, o1;
        o0.x = x0 > 0.f ? x0 : (__expf(x0) - 1.f);
        o0.y = x1 > 0.f ? x1 : (__expf(x1) - 1.f);
        o1.x = y0 > 0.f ? y0 : (__expf(y0) - 1.f);
        o1.y = y1 > 0.f ? y1 : (__expf(y1) - 1.f);
        *reinterpret_cast<float2*>(&out[(size_t)row0 * OUT_DIM + col]) = o0;
        *reinterpret_cast<float2*>(&out[(size_t)row1 * OUT_DIM + col]) = o1;
    }
}

// ---------------- launch ----------------
extern "C" void kernel_launch(void* const* d_in, const int* in_sizes, int n_in,
                              void* d_out, int out_size) {
    const float* H  = (const float*)d_in[0];
    const int*   A  = (const int*)  d_in[1];
    const float* W  = (const float*)d_in[2];
    const float* al = (const float*)d_in[3];
    const float* ar = (const float*)d_in[4];
    float* out = (float*)d_out;

    float*    Wh;    cudaGetSymbolAddress((void**)&Wh,    g_Wh);
    float*    WhT;   cudaGetSymbolAddress((void**)&WhT,   g_WhT);
    uint32_t* Amask; cudaGetSymbolAddress((void**)&Amask, g_Amask);
    float*    slT;   cudaGetSymbolAddress((void**)&slT,   g_slT);
    float*    srT;   cudaGetSymbolAddress((void**)&srT,   g_srT);
    float*    MT;    cudaGetSymbolAddress((void**)&MT,    g_MT);

    dim3 gA(OUT_DIM / 64, NN / 128);
    gemm_kernel<<<gA, 256>>>(H, W, Wh, WhT);

    score_kernel<<<NN, 128>>>(Wh, al, ar, slT, srT);

    rowmax_kernel<<<NN, 256>>>(A, slT, srT, MT, Amask);

    const int dyn_bytes = 2 * BUF_W * 4;   // 104448
    cudaFuncSetAttribute(attn_kernel, cudaFuncAttributeMaxDynamicSharedMemorySize, dyn_bytes);
    dim3 gC(NN / 64, HEADS);
    attn_kernel<<<gC, 256, dyn_bytes>>>(Amask, WhT, slT, srT, MT, out);
}